// round 1
// baseline (speedup 1.0000x reference)
#include <cuda_runtime.h>

// DisplacementMap (tfa dense_image_warp, bilinear) — B=8, H=512, W=512, C=16, fp32.
// Layout: x [B,H,W,C], flow [B,H,W,2], out [B,H,W,C], all row-major contiguous.
// out[b,h,w,c] = bilinear(x, h - flow[b,h,w,0], w - flow[b,h,w,1]) with
// floor clipped to [0,size-2] and alpha clipped to [0,1].

#define H_DIM 512
#define W_DIM 512
#define C_DIM 16
#define B_DIM 8

__global__ __launch_bounds__(256) void displacement_map_kernel(
    const float* __restrict__ x,
    const float* __restrict__ flow,
    float* __restrict__ out)
{
    // Each thread handles 4 channels (one float4) of one output pixel.
    // gid layout: [pixel][channel_group(0..3)] so stores are fully coalesced.
    const int gid = blockIdx.x * blockDim.x + threadIdx.x;
    const int cg  = gid & 3;          // channel group: 4 floats
    const int pix = gid >> 2;         // linear pixel index over B*H*W

    const int w = pix & (W_DIM - 1);
    const int h = (pix >> 9) & (H_DIM - 1);
    // b = pix >> 18 (implicit in linear addressing below)

    // flow is [.. ,2]: aligned float2 per pixel. 4 lanes per pixel read the
    // same 8 bytes -> L1 broadcast.
    const float2 f = reinterpret_cast<const float2*>(flow)[pix];

    const float qy = (float)h - f.x;
    const float qx = (float)w - f.y;

    float fy = floorf(qy);
    float fx = floorf(qx);
    fy = fminf(fmaxf(fy, 0.0f), (float)(H_DIM - 2));
    fx = fminf(fmaxf(fx, 0.0f), (float)(W_DIM - 2));

    const float ay = fminf(fmaxf(qy - fy, 0.0f), 1.0f);
    const float ax = fminf(fmaxf(qx - fx, 0.0f), 1.0f);

    const int iy = (int)fy;
    const int ix = (int)fx;
    const int b_hw = pix >> 18;  // batch

    // Base address of x[b, iy, ix, 0] in float4 units.
    // ((b*H + iy)*W + ix)*C floats ; /4 -> float4
    const size_t base_f4 =
        ((((size_t)b_hw * H_DIM + (size_t)iy) * W_DIM + (size_t)ix) * C_DIM) >> 2;

    const float4* __restrict__ xf4 = reinterpret_cast<const float4*>(x);

    // Four independent gathers (MLP=4):
    //   top-left  = base + cg
    //   top-right = base + cg + C/4      (ix+1)
    //   bottom-*  = + W*C/4              (iy+1)
    const size_t row_stride_f4 = (size_t)W_DIM * C_DIM / 4;  // 2048

    const float4 tl = xf4[base_f4 + cg];
    const float4 tr = xf4[base_f4 + cg + (C_DIM / 4)];
    const float4 bl = xf4[base_f4 + cg + row_stride_f4];
    const float4 br = xf4[base_f4 + cg + row_stride_f4 + (C_DIM / 4)];

    float4 r;
    {
        const float tx0 = tl.x + ax * (tr.x - tl.x);
        const float tx1 = tl.y + ax * (tr.y - tl.y);
        const float tx2 = tl.z + ax * (tr.z - tl.z);
        const float tx3 = tl.w + ax * (tr.w - tl.w);
        const float bx0 = bl.x + ax * (br.x - bl.x);
        const float bx1 = bl.y + ax * (br.y - bl.y);
        const float bx2 = bl.z + ax * (br.z - bl.z);
        const float bx3 = bl.w + ax * (br.w - bl.w);
        r.x = tx0 + ay * (bx0 - tx0);
        r.y = tx1 + ay * (bx1 - tx1);
        r.z = tx2 + ay * (bx2 - tx2);
        r.w = tx3 + ay * (bx3 - tx3);
    }

    reinterpret_cast<float4*>(out)[gid] = r;
}

extern "C" void kernel_launch(void* const* d_in, const int* in_sizes, int n_in,
                              void* d_out, int out_size)
{
    const float* x    = (const float*)d_in[0];
    const float* flow = (const float*)d_in[1];
    float* out        = (float*)d_out;

    // total threads = B*H*W*4 (4 channel-groups per pixel)
    const int total = B_DIM * H_DIM * W_DIM * 4;  // 8,388,608
    const int block = 256;
    const int grid  = total / block;              // 32768

    displacement_map_kernel<<<grid, block>>>(x, flow, out);
}

// round 2
// speedup vs baseline: 1.0005x; 1.0005x over previous
#include <cuda_runtime.h>

// DisplacementMap (tfa dense_image_warp, bilinear) — B=8, H=512, W=512, C=16, fp32.
// R2: 2 pixel/channel-group units per thread for doubled memory-level
// parallelism (2 flow loads front-batched, then 8 corner gathers front-batched).
// Units split as [gid, gid + TOTAL/2] so stores remain fully coalesced.

#define H_DIM 512
#define W_DIM 512
#define C_DIM 16
#define B_DIM 8

#define TOTAL_UNITS (B_DIM * H_DIM * W_DIM * 4)   // 8,388,608 channel-group units
#define HALF_UNITS  (TOTAL_UNITS / 2)             // 4,194,304

__global__ __launch_bounds__(256) void displacement_map_kernel(
    const float* __restrict__ x,
    const float* __restrict__ flow,
    float* __restrict__ out)
{
    const int gid = blockIdx.x * blockDim.x + threadIdx.x;

    const int u0 = gid;
    const int u1 = gid + HALF_UNITS;

    const int cg0  = u0 & 3;
    const int pix0 = u0 >> 2;
    const int cg1  = u1 & 3;
    const int pix1 = u1 >> 2;

    // Phase 1: both flow loads issue independently (MLP=2).
    const float2 f0 = reinterpret_cast<const float2*>(flow)[pix0];
    const float2 f1 = reinterpret_cast<const float2*>(flow)[pix1];

    // ---- index math for unit 0 ----
    const int w0 = pix0 & (W_DIM - 1);
    const int h0 = (pix0 >> 9) & (H_DIM - 1);
    const float qy0 = (float)h0 - f0.x;
    const float qx0 = (float)w0 - f0.y;
    float fy0 = fminf(fmaxf(floorf(qy0), 0.0f), (float)(H_DIM - 2));
    float fx0 = fminf(fmaxf(floorf(qx0), 0.0f), (float)(W_DIM - 2));
    const float ay0 = fminf(fmaxf(qy0 - fy0, 0.0f), 1.0f);
    const float ax0 = fminf(fmaxf(qx0 - fx0, 0.0f), 1.0f);
    const int iy0 = (int)fy0;
    const int ix0 = (int)fx0;
    const size_t base0 =
        ((((size_t)(pix0 >> 18) * H_DIM + (size_t)iy0) * W_DIM + (size_t)ix0) * C_DIM) >> 2;

    // ---- index math for unit 1 ----
    const int w1 = pix1 & (W_DIM - 1);
    const int h1 = (pix1 >> 9) & (H_DIM - 1);
    const float qy1 = (float)h1 - f1.x;
    const float qx1 = (float)w1 - f1.y;
    float fy1 = fminf(fmaxf(floorf(qy1), 0.0f), (float)(H_DIM - 2));
    float fx1 = fminf(fmaxf(floorf(qx1), 0.0f), (float)(W_DIM - 2));
    const float ay1 = fminf(fmaxf(qy1 - fy1, 0.0f), 1.0f);
    const float ax1 = fminf(fmaxf(qx1 - fx1, 0.0f), 1.0f);
    const int iy1 = (int)fy1;
    const int ix1 = (int)fx1;
    const size_t base1 =
        ((((size_t)(pix1 >> 18) * H_DIM + (size_t)iy1) * W_DIM + (size_t)ix1) * C_DIM) >> 2;

    const float4* __restrict__ xf4 = reinterpret_cast<const float4*>(x);
    const size_t row_f4 = (size_t)W_DIM * C_DIM / 4;  // 2048

    // Phase 2: all 8 corner gathers front-batched (MLP=8).
    const float4 tl0 = xf4[base0 + cg0];
    const float4 tr0 = xf4[base0 + cg0 + (C_DIM / 4)];
    const float4 bl0 = xf4[base0 + cg0 + row_f4];
    const float4 br0 = xf4[base0 + cg0 + row_f4 + (C_DIM / 4)];
    const float4 tl1 = xf4[base1 + cg1];
    const float4 tr1 = xf4[base1 + cg1 + (C_DIM / 4)];
    const float4 bl1 = xf4[base1 + cg1 + row_f4];
    const float4 br1 = xf4[base1 + cg1 + row_f4 + (C_DIM / 4)];

    float4 r0, r1;
    {
        float t, b;
        t = tl0.x + ax0 * (tr0.x - tl0.x); b = bl0.x + ax0 * (br0.x - bl0.x);
        r0.x = t + ay0 * (b - t);
        t = tl0.y + ax0 * (tr0.y - tl0.y); b = bl0.y + ax0 * (br0.y - bl0.y);
        r0.y = t + ay0 * (b - t);
        t = tl0.z + ax0 * (tr0.z - tl0.z); b = bl0.z + ax0 * (br0.z - bl0.z);
        r0.z = t + ay0 * (b - t);
        t = tl0.w + ax0 * (tr0.w - tl0.w); b = bl0.w + ax0 * (br0.w - bl0.w);
        r0.w = t + ay0 * (b - t);

        t = tl1.x + ax1 * (tr1.x - tl1.x); b = bl1.x + ax1 * (br1.x - bl1.x);
        r1.x = t + ay1 * (b - t);
        t = tl1.y + ax1 * (tr1.y - tl1.y); b = bl1.y + ax1 * (br1.y - bl1.y);
        r1.y = t + ay1 * (b - t);
        t = tl1.z + ax1 * (tr1.z - tl1.z); b = bl1.z + ax1 * (br1.z - bl1.z);
        r1.z = t + ay1 * (b - t);
        t = tl1.w + ax1 * (tr1.w - tl1.w); b = bl1.w + ax1 * (br1.w - bl1.w);
        r1.w = t + ay1 * (b - t);
    }

    reinterpret_cast<float4*>(out)[u0] = r0;
    reinterpret_cast<float4*>(out)[u1] = r1;
}

extern "C" void kernel_launch(void* const* d_in, const int* in_sizes, int n_in,
                              void* d_out, int out_size)
{
    const float* x    = (const float*)d_in[0];
    const float* flow = (const float*)d_in[1];
    float* out        = (float*)d_out;

    const int threads = HALF_UNITS;        // 4,194,304
    const int block   = 256;
    const int grid    = threads / block;   // 16384

    displacement_map_kernel<<<grid, block>>>(x, flow, out);
}